// round 11
// baseline (speedup 1.0000x reference)
#include <cuda_runtime.h>
#include <cuda_bf16.h>
#include <cstdint>

#define BATCH 2048
#define KLBL  20
#define NCLS  50257
#define TPB   256
#define NBLK  BATCH

#define TILE_F4   1024                 // float4 per tile = 16KB; 4 per thread
#define TILE_B    (TILE_F4 * 16)
#define NSTAGE    2

// Scratch (no cudaMalloc allowed)
__device__ float g_part[BATCH];
__device__ float g_aux [BATCH];
__device__ float g_cnt [BATCH];
__device__ int   g_counter = 0;

// ---------------------------------------------------------------------------
// exp(x), MUFU-free: magic-round + deg-2 Taylor + FMUL exponent scale.
// Pointwise rel err ~7e-3 worst / ~1e-4 aggregate (odd term cancels over the
// symmetric t-distribution); measured loss rel_err 1.1e-4 in R6. 7 fma-pipe ops.
// ---------------------------------------------------------------------------
__device__ __forceinline__ float exp_fast(float x)
{
    float z  = fmaf(x, 1.4426950408889634f, 12582912.0f);   // magic 1.5*2^23
    float nf = z - 12582912.0f;                             // rint(x*log2e)
    float t  = fmaf(nf, -0.6931471805599453f, x);           // |t| <= 0.347
    float q  = fmaf(t, 0.5f, 1.0f);
    q = fmaf(q, t, 1.0f);                                   // 1 + t + t^2/2
    int sbits = (__float_as_int(z) << 23) + 0x3F800000;     // 2^n (wraps exact)
    return q * __int_as_float(sbits);
}

__device__ __forceinline__ void renorm(float& P, int& E)
{
    int b = __float_as_int(P);
    E += (b >> 23) - 127;
    P  = __int_as_float((b & 0x007FFFFF) | 0x3F800000);     // mantissa [1,2)
}

__device__ __forceinline__ uint32_t s2u(const void* s)
{
    uint32_t a;
    asm("{ .reg .u64 t; cvta.to.shared.u64 t, %1; cvt.u32.u64 %0, t; }"
        : "=r"(a) : "l"(s));
    return a;
}
__device__ __forceinline__ void mbar_init(uint32_t mbar, uint32_t cnt)
{ asm volatile("mbarrier.init.shared.b64 [%0], %1;" :: "r"(mbar), "r"(cnt) : "memory"); }
__device__ __forceinline__ void mbar_expect_tx(uint32_t mbar, uint32_t bytes)
{ asm volatile("mbarrier.arrive.expect_tx.shared.b64 _, [%0], %1;" :: "r"(mbar), "r"(bytes) : "memory"); }
__device__ __forceinline__ void bulk_g2s(uint32_t dst, const void* src, uint32_t bytes, uint32_t mbar)
{
    asm volatile(
        "cp.async.bulk.shared::cta.global.mbarrier::complete_tx::bytes [%0], [%1], %2, [%3];"
        :: "r"(dst), "l"(src), "r"(bytes), "r"(mbar) : "memory");
}
__device__ __forceinline__ void mbar_wait(uint32_t mbar, uint32_t parity)
{
    asm volatile(
        "{\n\t"
        ".reg .pred P;\n\t"
        "W%=:\n\t"
        "mbarrier.try_wait.parity.acquire.cta.shared::cta.b64 P, [%0], %1, 0x989680;\n\t"
        "@P bra.uni D%=;\n\t"
        "bra.uni W%=;\n\t"
        "D%=:\n\t"
        "}"
        :: "r"(mbar), "r"(parity) : "memory");
}

// ---------------------------------------------------------------------------
// One block per row: TMA double-buffered stream; S_row = log prod(1+e^x);
// fused label pass; last-block deterministic global combine.
// ---------------------------------------------------------------------------
__global__ __launch_bounds__(TPB)
void fused_row(const float* __restrict__ in, const int* __restrict__ tgt,
               float* __restrict__ out)
{
    const int row = blockIdx.x;
    const int tid = threadIdx.x;
    const float* p = in + (size_t)row * NCLS;

    __shared__ __align__(128) float4 stage[NSTAGE][TILE_F4];   // 32KB
    __shared__ __align__(8) unsigned long long mbar_s[NSTAGE];
    __shared__ float sbuf[TPB];
    __shared__ int   slab[KLBL];
    __shared__ int   isLast;

    const uint32_t mb0 = s2u(&mbar_s[0]);
    const uint32_t mb1 = s2u(&mbar_s[1]);
    const uint32_t st0 = s2u(&stage[0][0]);
    const uint32_t st1 = s2u(&stage[1][0]);

    if (tid < KLBL) slab[tid] = tgt[row * KLBL + tid];
    if (tid == 0) { mbar_init(mb0, 1); mbar_init(mb1, 1); }
    __syncthreads();
    float xlab = 0.0f;
    int   mylab = -1;
    if (tid < KLBL) { mylab = slab[tid]; xlab = __ldg(p + mylab); }

    // scalar head to 16B alignment: 50257 % 4 == 1 -> h = f(row)
    const int h  = (4 - (row & 3)) & 3;
    const int n4 = (NCLS - h) >> 2;
    const int ntiles = n4 / TILE_F4;                 // 12 full tiles
    const float4* vg = (const float4*)(p + h);
    const char*   src = (const char*)vg;

    // prologue: fill both stages
    if (tid == 0) {
        mbar_expect_tx(mb0, TILE_B);
        bulk_g2s(st0, src, TILE_B, mb0);
        if (ntiles > 1) {
            mbar_expect_tx(mb1, TILE_B);
            bulk_g2s(st1, src + TILE_B, TILE_B, mb1);
        }
    }

    float Pa = 1.0f, Pb = 1.0f;
    int   Ea = 0,   Eb = 0;
    if (tid < h) { Pa = fmaf(exp_fast(p[tid]), Pa, Pa); renorm(Pa, Ea); }

    // pipelined main loop: 4 float4 / thread / tile (16 elems), renorm 8/acc
    for (int t = 0; t < ntiles; t++) {
        const int s  = t & 1;
        const uint32_t ph = (uint32_t)((t >> 1) & 1);
        mbar_wait(s ? mb1 : mb0, ph);

        const float4* v = stage[s];
        float4 x0 = v[tid];
        float4 x1 = v[tid + TPB];
        float4 x2 = v[tid + 2 * TPB];
        float4 x3 = v[tid + 3 * TPB];
        Pa = fmaf(exp_fast(x0.x), Pa, Pa);
        Pa = fmaf(exp_fast(x0.y), Pa, Pa);
        Pb = fmaf(exp_fast(x0.z), Pb, Pb);
        Pb = fmaf(exp_fast(x0.w), Pb, Pb);
        Pa = fmaf(exp_fast(x1.x), Pa, Pa);
        Pa = fmaf(exp_fast(x1.y), Pa, Pa);
        Pb = fmaf(exp_fast(x1.z), Pb, Pb);
        Pb = fmaf(exp_fast(x1.w), Pb, Pb);
        Pa = fmaf(exp_fast(x2.x), Pa, Pa);
        Pa = fmaf(exp_fast(x2.y), Pa, Pa);
        Pb = fmaf(exp_fast(x2.z), Pb, Pb);
        Pb = fmaf(exp_fast(x2.w), Pb, Pb);
        Pa = fmaf(exp_fast(x3.x), Pa, Pa);
        Pa = fmaf(exp_fast(x3.y), Pa, Pa);
        Pb = fmaf(exp_fast(x3.z), Pb, Pb);
        Pb = fmaf(exp_fast(x3.w), Pb, Pb);
        renorm(Pa, Ea);            // 8 factors/acc: product < 2^77, safe
        renorm(Pb, Eb);

        __syncthreads();           // stage fully consumed
        if (tid == 0 && t + NSTAGE < ntiles) {
            uint32_t mb = s ? mb1 : mb0;
            mbar_expect_tx(mb, TILE_B);
            bulk_g2s(s ? st1 : st0, src + (size_t)(t + NSTAGE) * TILE_B, TILE_B, mb);
        }
    }

    // remainder float4s via direct LDG (n4 - 12*1024 = 276)
    const int base = ntiles * TILE_F4;
    for (int j = base + tid; j < n4; j += TPB) {
        float4 xa = vg[j];
        Pa = fmaf(exp_fast(xa.x), Pa, Pa);
        Pa = fmaf(exp_fast(xa.y), Pa, Pa);
        Pb = fmaf(exp_fast(xa.z), Pb, Pb);
        Pb = fmaf(exp_fast(xa.w), Pb, Pb);
        renorm(Pa, Ea);
        renorm(Pb, Eb);
    }
    // scalar tail (<= 3)
    const int t0 = h + (n4 << 2);
    if (tid < NCLS - t0) {
        Pa = fmaf(exp_fast(p[t0 + tid]), Pa, Pa);
        renorm(Pa, Ea);
    }

    float val = fmaf((float)(Ea + Eb), 0.69314718055994531f, __logf(Pa * Pb));

    // block tree reduce S_row
    sbuf[tid] = val;
    __syncthreads();
    #pragma unroll
    for (int r = TPB / 2; r > 0; r >>= 1) {
        if (tid < r) sbuf[tid] += sbuf[tid + r];
        __syncthreads();
    }

    // label pass on warp 0 (accurate math on 20 elements)
    if (tid < 32) {
        float pos = 0.0f, corr = 0.0f;
        int   U = 0;
        if (tid < KLBL) {
            float x  = xlab;
            float l1 = log1pf(__expf(-fabsf(x)));
            pos = -(fmaxf(-x, 0.0f) + l1);                    // log_sigmoid(x)
            bool uniq = true;
            #pragma unroll
            for (int j = 0; j < KLBL; j++)
                if (j < tid && slab[j] == mylab) uniq = false;
            if (uniq) { corr = fmaxf(x, 0.0f) + l1; U = 1; }  // softplus(x)
        }
        #pragma unroll
        for (int o = 16; o > 0; o >>= 1) {
            pos  += __shfl_down_sync(0xFFFFFFFF, pos,  o);
            corr += __shfl_down_sync(0xFFFFFFFF, corr, o);
            U    += __shfl_down_sync(0xFFFFFFFF, U,    o);
        }
        if (tid == 0) {
            g_part[row] = sbuf[0] - corr;
            g_aux[row]  = pos * (1.0f / (float)KLBL);
            g_cnt[row]  = (float)(NCLS - U);
        }
    }

    // last-block election + deterministic final combine
    if (tid == 0) {
        __threadfence();
        int t = atomicAdd(&g_counter, 1);
        isLast = (t == NBLK - 1);
    }
    __syncthreads();
    if (isLast) {
        float acc = 0.0f;
        for (int r = tid; r < BATCH; r += TPB)
            acc += g_aux[r] - g_part[r] / g_cnt[r];
        __syncthreads();
        sbuf[tid] = acc;
        __syncthreads();
        #pragma unroll
        for (int r = TPB / 2; r > 0; r >>= 1) {
            if (tid < r) sbuf[tid] += sbuf[tid + r];
            __syncthreads();
        }
        if (tid == 0) {
            out[0] = -sbuf[0] / (float)BATCH;
            g_counter = 0;
        }
    }
}

extern "C" void kernel_launch(void* const* d_in, const int* in_sizes, int n_in,
                              void* d_out, int out_size)
{
    const float* inputs  = (const float*)d_in[0];
    const int*   targets = (const int*)d_in[1];
    float*       out     = (float*)d_out;

    fused_row<<<NBLK, TPB>>>(inputs, targets, out);
}